// round 10
// baseline (speedup 1.0000x reference)
#include <cuda_runtime.h>
#include <cuda_fp16.h>
#include <mma.h>
#include <cstdint>

using namespace nvcuda;

#define NN 100000
#define NN_PAD 100096   // 782 * 128
#define MAXE 3300000
#define SCAN_BS 512

// ---------------- scratch (static device globals; zero-initialized) ---------
__device__ __align__(256) int    g_indeg[NN];
__device__ __align__(256) int    g_outdeg[NN];
__device__ __align__(256) int    g_fill[NN];
__device__ __align__(256) int    g_rowptr[NN + 1];
__device__ __align__(256) int    g_blocksums[256];
__device__ __align__(256) int    g_esrc[MAXE];
__device__ __align__(256) float  g_snorm[NN];
__device__ __align__(256) float  g_dnorm[NN];
__device__ __align__(256) __half g_xh[(size_t)NN_PAD * 256];    // feat fp16
__device__ __align__(256) __half g_aggh[(size_t)NN_PAD * 256];  // agg fp16
__device__ __align__(256) __half g_hh[(size_t)NN_PAD * 256];    // h fp16
__device__ __align__(256) __half g_xmh[(size_t)NN_PAD * 64];    // xm fp16
__device__ __align__(256) __half g_w0h[256 * 256];
__device__ __align__(256) __half g_w1h[256 * 256];
__device__ __align__(256) __half g_w2h[256 * 64];

// ---------------- degrees --------------------------------------------------
__global__ void zero_init_kernel() {
    int i = blockIdx.x * blockDim.x + threadIdx.x;
    if (i < NN) { g_indeg[i] = 0; g_outdeg[i] = 0; }
}

__global__ void degree_kernel(const int* __restrict__ src,
                              const int* __restrict__ dst, int nE) {
    int i = blockIdx.x * blockDim.x + threadIdx.x;
    if (i < nE) {
        atomicAdd(&g_outdeg[src[i]], 1);
        atomicAdd(&g_indeg[dst[i]], 1);
    }
}

// ---------------- CSR build (norms fused into scan3) -------------------------
__global__ void scan1_kernel() {
    __shared__ int sh[SCAN_BS];
    int i = blockIdx.x * SCAN_BS + threadIdx.x;
    int v = (i < NN) ? g_indeg[i] : 0;
    sh[threadIdx.x] = v;
    __syncthreads();
    for (int off = 1; off < SCAN_BS; off <<= 1) {
        int t = (threadIdx.x >= off) ? sh[threadIdx.x - off] : 0;
        __syncthreads();
        sh[threadIdx.x] += t;
        __syncthreads();
    }
    if (i < NN) g_rowptr[i] = sh[threadIdx.x] - v;
    if (threadIdx.x == SCAN_BS - 1) g_blocksums[blockIdx.x] = sh[threadIdx.x];
}

__global__ void scan2_kernel(int nb) {
    __shared__ int sh[256];
    int t = threadIdx.x;
    int v = (t < nb) ? g_blocksums[t] : 0;
    sh[t] = v;
    __syncthreads();
    for (int off = 1; off < 256; off <<= 1) {
        int u = (t >= off) ? sh[t - off] : 0;
        __syncthreads();
        sh[t] += u;
        __syncthreads();
    }
    if (t < nb) g_blocksums[t] = sh[t] - v;
}

// finalizes rowptr, seeds fill counters, computes both norms
__global__ void scan3_kernel(int nE) {
    int i = blockIdx.x * SCAN_BS + threadIdx.x;
    if (i < NN) {
        int rp = g_rowptr[i] + g_blocksums[blockIdx.x];
        g_rowptr[i] = rp;
        g_fill[i] = rp;
        g_snorm[i] = rsqrtf(fmaxf((float)g_outdeg[i], 1.f));
        g_dnorm[i] = rsqrtf(fmaxf((float)g_indeg[i], 1.f));
    }
    if (i == 0) g_rowptr[NN] = nE;
}

__global__ void fillcsr_kernel(const int* __restrict__ src,
                               const int* __restrict__ dst, int nE) {
    int i = blockIdx.x * blockDim.x + threadIdx.x;
    if (i < nE) {
        int pos = atomicAdd(&g_fill[dst[i]], 1);
        g_esrc[pos] = src[i];
    }
}

// ---------------- fp32 -> fp16 converts --------------------------------------
__global__ void convert_half_kernel(const float* __restrict__ in,
                                    __half* __restrict__ out, int n8) {
    int i = blockIdx.x * blockDim.x + threadIdx.x;
    if (i >= n8) return;
    float4 a = ((const float4*)in)[i * 2];
    float4 b = ((const float4*)in)[i * 2 + 1];
    __half2 h[4];
    h[0] = __floats2half2_rn(a.x, a.y);
    h[1] = __floats2half2_rn(a.z, a.w);
    h[2] = __floats2half2_rn(b.x, b.y);
    h[3] = __floats2half2_rn(b.z, b.w);
    ((uint4*)out)[i] = *(const uint4*)h;
}

// all three weights in one launch. W0:[0,8192) W1:[8192,16384) W2:[16384,18432)
__global__ void convert_weights_kernel(const float* __restrict__ W0,
                                       const float* __restrict__ W1,
                                       const float* __restrict__ W2) {
    int i = blockIdx.x * blockDim.x + threadIdx.x;
    const float* in;
    __half* out;
    int off;
    if (i < 8192) { in = W0; out = g_w0h; off = i; }
    else if (i < 16384) { in = W1; out = g_w1h; off = i - 8192; }
    else if (i < 18432) { in = W2; out = g_w2h; off = i - 16384; }
    else return;
    float4 a = ((const float4*)in)[off * 2];
    float4 b = ((const float4*)in)[off * 2 + 1];
    __half2 h[4];
    h[0] = __floats2half2_rn(a.x, a.y);
    h[1] = __floats2half2_rn(a.z, a.w);
    h[2] = __floats2half2_rn(b.x, b.y);
    h[3] = __floats2half2_rn(b.z, b.w);
    ((uint4*)out)[off] = *(const uint4*)h;
}

// ---------------- gather256: fp16 in, fp32 accum, fp16 out -------------------
// prefetched edge batches + 8-edge unroll (8 LDG.128 in flight)
__global__ __launch_bounds__(256) void gather256h_kernel(
    const __half* __restrict__ x, __half* __restrict__ out) {
    int v = (blockIdx.x * blockDim.x + threadIdx.x) >> 5;
    int lane = threadIdx.x & 31;
    if (v >= NN) return;
    int row = g_rowptr[v];
    int end = g_rowptr[v + 1];
    float acc[8] = {0.f, 0.f, 0.f, 0.f, 0.f, 0.f, 0.f, 0.f};

    int s = 0;
    float w = 0.f;
    if (row < end) {
        int n0 = min(32, end - row);
        if (lane < n0) { s = __ldg(&g_esrc[row + lane]); w = __ldg(&g_snorm[s]); }
    }

    for (int base = row; base < end; base += 32) {
        int n = min(32, end - base);
        // prefetch next batch's indices + norms
        int sn = 0;
        float wn = 0.f;
        if (base + 32 < end) {
            int n2 = min(32, end - base - 32);
            if (lane < n2) {
                sn = __ldg(&g_esrc[base + 32 + lane]);
                wn = __ldg(&g_snorm[sn]);
            }
        }
        int k = 0;
        for (; k + 8 <= n; k += 8) {
            int si[8];
            float wi[8];
            uint4 u[8];
#pragma unroll
            for (int e = 0; e < 8; e++) {
                si[e] = __shfl_sync(0xffffffffu, s, k + e);
                wi[e] = __shfl_sync(0xffffffffu, w, k + e);
            }
#pragma unroll
            for (int e = 0; e < 8; e++)
                u[e] = __ldg((const uint4*)(x + (size_t)si[e] * 256) + lane);
#pragma unroll
            for (int e = 0; e < 8; e++) {
                const __half2* p = (const __half2*)&u[e];
#pragma unroll
                for (int j = 0; j < 4; j++) {
                    float2 f = __half22float2(p[j]);
                    acc[j * 2 + 0] += wi[e] * f.x;
                    acc[j * 2 + 1] += wi[e] * f.y;
                }
            }
        }
        for (; k < n; k++) {
            int s0 = __shfl_sync(0xffffffffu, s, k);
            float w0 = __shfl_sync(0xffffffffu, w, k);
            uint4 u0 = __ldg((const uint4*)(x + (size_t)s0 * 256) + lane);
            const __half2* p0 = (const __half2*)&u0;
#pragma unroll
            for (int j = 0; j < 4; j++) {
                float2 f0 = __half22float2(p0[j]);
                acc[j * 2 + 0] += w0 * f0.x;
                acc[j * 2 + 1] += w0 * f0.y;
            }
        }
        s = sn;
        w = wn;
    }
    __half2 hv[4];
#pragma unroll
    for (int j = 0; j < 4; j++)
        hv[j] = __floats2half2_rn(acc[j * 2], acc[j * 2 + 1]);
    ((uint4*)(out + (size_t)v * 256))[lane] = *(const uint4*)hv;
}

// ---------------- gather64: fp16 in, fp32 out --------------------------------
__global__ __launch_bounds__(256) void gather64h_kernel(
    const __half* __restrict__ x, float* __restrict__ out) {
    int v = (blockIdx.x * blockDim.x + threadIdx.x) >> 5;
    int lane = threadIdx.x & 31;
    if (v >= NN) return;
    int row = g_rowptr[v];
    int end = g_rowptr[v + 1];
    float2 acc = make_float2(0.f, 0.f);

    int s = 0;
    if (row < end) {
        int n0 = min(32, end - row);
        if (lane < n0) s = __ldg(&g_esrc[row + lane]);
    }

    for (int base = row; base < end; base += 32) {
        int n = min(32, end - base);
        int sn = 0;
        if (base + 32 < end) {
            int n2 = min(32, end - base - 32);
            if (lane < n2) sn = __ldg(&g_esrc[base + 32 + lane]);
        }
        int k = 0;
        for (; k + 8 <= n; k += 8) {
            __half2 a[8];
#pragma unroll
            for (int e = 0; e < 8; e++) {
                int se = __shfl_sync(0xffffffffu, s, k + e);
                a[e] = __ldg((const __half2*)(x + (size_t)se * 64) + lane);
            }
#pragma unroll
            for (int e = 0; e < 8; e++) {
                float2 f = __half22float2(a[e]);
                acc.x += f.x;
                acc.y += f.y;
            }
        }
        for (; k < n; k++) {
            int s0 = __shfl_sync(0xffffffffu, s, k);
            float2 f0 = __half22float2(__ldg((const __half2*)(x + (size_t)s0 * 64) + lane));
            acc.x += f0.x;
            acc.y += f0.y;
        }
        s = sn;
    }
    float w = g_dnorm[v];
    ((float2*)(out + (size_t)v * 64))[lane] = make_float2(acc.x * w, acc.y * w);
}

// ---------------- fp16 tensor-core GEMM, BK=64 -------------------------------
template <int BN, bool RELU>
__global__ __launch_bounds__(256, 2) void gemm_h_kernel(
    const __half* __restrict__ A, const __half* __restrict__ Wh,
    const float* __restrict__ norm, __half* __restrict__ C, int M, int N) {
    constexpr int BM = 128, BK = 64;
    constexpr int WM = (BN == 128) ? 64 : 32;
    constexpr int FM = WM / 16;
    constexpr int BQ = (BN == 128) ? 4 : 2;
    __shared__ __half As[BM][BK + 8];
    __shared__ __half Bs[BK][BN + 8];
    __shared__ float  stage[8][16 * 24];

    const int t = threadIdx.x;
    const int warp = t >> 5;
    const int lane = t & 31;
    const int wm = (BN == 128) ? (warp >> 2) : (warp >> 1);
    const int wn = (BN == 128) ? (warp & 3) : (warp & 1);
    const int row0 = blockIdx.x * BM;
    const int col0 = blockIdx.y * BN;

    const int a_row = t >> 1;
    const int a_c0 = (t & 1) * 32;
    const bool a_ok = (row0 + a_row) < M;
    const float nrmf = a_ok ? __ldg(&norm[row0 + a_row]) : 0.f;
    const __half2 nrm2 = __float2half2_rn(nrmf);
    const __half* Aptr = A + (size_t)(row0 + a_row) * 256 + a_c0;

    const int b_row = t >> 2;
    const int b_c0 = (t & 3) * 8 * BQ;

    wmma::fragment<wmma::accumulator, 16, 16, 16, float> acc[FM][2];
#pragma unroll
    for (int i = 0; i < FM; i++)
#pragma unroll
        for (int j = 0; j < 2; j++) wmma::fill_fragment(acc[i][j], 0.f);

    uint4 ar[4], br[BQ];
#pragma unroll
    for (int q = 0; q < 4; q++) ar[q] = *(const uint4*)(Aptr + q * 8);
#pragma unroll
    for (int q = 0; q < BQ; q++)
        br[q] = *(const uint4*)&Wh[(size_t)b_row * N + col0 + b_c0 + q * 8];

    auto store_tiles = [&]() {
#pragma unroll
        for (int q = 0; q < 4; q++) {
            const __half2* p = (const __half2*)&ar[q];
            __half2* dstp = (__half2*)&As[a_row][a_c0 + q * 8];
#pragma unroll
            for (int j = 0; j < 4; j++) dstp[j] = __hmul2(p[j], nrm2);
        }
#pragma unroll
        for (int q = 0; q < BQ; q++)
            *(uint4*)&Bs[b_row][b_c0 + q * 8] = br[q];
    };

    store_tiles();
    __syncthreads();

    for (int k0 = 0; k0 < 256; k0 += BK) {
        const bool has_next = (k0 + BK) < 256;
        if (has_next) {
#pragma unroll
            for (int q = 0; q < 4; q++)
                ar[q] = *(const uint4*)(Aptr + k0 + BK + q * 8);
#pragma unroll
            for (int q = 0; q < BQ; q++)
                br[q] = *(const uint4*)&Wh[(size_t)(k0 + BK + b_row) * N + col0 + b_c0 + q * 8];
        }
#pragma unroll
        for (int kk = 0; kk < BK; kk += 16) {
            wmma::fragment<wmma::matrix_a, 16, 16, 16, __half, wmma::row_major> af[FM];
            wmma::fragment<wmma::matrix_b, 16, 16, 16, __half, wmma::row_major> bf[2];
#pragma unroll
            for (int i = 0; i < FM; i++)
                wmma::load_matrix_sync(af[i], &As[wm * WM + i * 16][kk], BK + 8);
#pragma unroll
            for (int j = 0; j < 2; j++)
                wmma::load_matrix_sync(bf[j], &Bs[kk][wn * 32 + j * 16], BN + 8);
#pragma unroll
            for (int i = 0; i < FM; i++)
#pragma unroll
                for (int j = 0; j < 2; j++)
                    wmma::mma_sync(acc[i][j], af[i], bf[j], acc[i][j]);
        }
        __syncthreads();
        if (has_next) {
            store_tiles();
            __syncthreads();
        }
    }

#pragma unroll
    for (int i = 0; i < FM; i++)
#pragma unroll
        for (int j = 0; j < 2; j++) {
            if (RELU) {
#pragma unroll
                for (int e = 0; e < acc[i][j].num_elements; e++)
                    acc[i][j].x[e] = fmaxf(acc[i][j].x[e], 0.f);
            }
            wmma::store_matrix_sync(&stage[warp][0], acc[i][j], 24,
                                    wmma::mem_row_major);
            __syncwarp();
            int r = lane >> 1;
            int ch = (lane & 1) * 8;
            const float* sp = &stage[warp][r * 24 + ch];
            __half2 hv[4];
#pragma unroll
            for (int q = 0; q < 4; q++)
                hv[q] = __floats2half2_rn(sp[q * 2], sp[q * 2 + 1]);
            __half* cp = C + (size_t)(row0 + wm * WM + i * 16 + r) * N +
                         col0 + wn * 32 + j * 16 + ch;
            *(uint4*)cp = *(const uint4*)hv;
            __syncwarp();
        }
}

// ---------------- launch -----------------------------------------------------
extern "C" void kernel_launch(void* const* d_in, const int* in_sizes, int n_in,
                              void* d_out, int out_size) {
    const float* feat = (const float*)d_in[0];
    const int* src = (const int*)d_in[1];
    const int* dst = (const int*)d_in[2];
    const float* W0 = (const float*)d_in[3];
    const float* W1 = (const float*)d_in[4];
    const float* W2 = (const float*)d_in[5];
    float* out = (float*)d_out;
    const int nE = in_sizes[1];

    __half *xh, *aggh, *hh, *xmh, *w0h, *w1h, *w2h;
    float *snorm, *dnorm;
    cudaGetSymbolAddress((void**)&xh, g_xh);
    cudaGetSymbolAddress((void**)&aggh, g_aggh);
    cudaGetSymbolAddress((void**)&hh, g_hh);
    cudaGetSymbolAddress((void**)&xmh, g_xmh);
    cudaGetSymbolAddress((void**)&w0h, g_w0h);
    cudaGetSymbolAddress((void**)&w1h, g_w1h);
    cudaGetSymbolAddress((void**)&w2h, g_w2h);
    cudaGetSymbolAddress((void**)&snorm, g_snorm);
    cudaGetSymbolAddress((void**)&dnorm, g_dnorm);

    const int T = 256;
    const int NB = (NN + SCAN_BS - 1) / SCAN_BS;      // 196
    const int gemm_rows = NN_PAD / 128;               // 782
    const int gather_blocks = (NN * 32 + T - 1) / T;  // 12500
    const int conv8 = NN * 256 / 8;

    // lazily-created side stream + fork/join events (host-side resources only)
    static cudaStream_t s_side = nullptr;
    static cudaEvent_t ev_fork = nullptr, ev_join = nullptr;
    if (s_side == nullptr) {
        if (cudaStreamCreateWithFlags(&s_side, cudaStreamNonBlocking) != cudaSuccess)
            s_side = nullptr;
        cudaEventCreateWithFlags(&ev_fork, cudaEventDisableTiming);
        cudaEventCreateWithFlags(&ev_join, cudaEventDisableTiming);
    }
    const bool use_side = (s_side != nullptr);

    // ---- branch A (side stream): fp32->fp16 converts (independent of CSR) ---
    if (use_side) {
        cudaEventRecord(ev_fork, 0);
        cudaStreamWaitEvent(s_side, ev_fork, 0);
        convert_half_kernel<<<(conv8 + T - 1) / T, T, 0, s_side>>>(feat, xh, conv8);
        convert_weights_kernel<<<(18432 + T - 1) / T, T, 0, s_side>>>(W0, W1, W2);
        cudaEventRecord(ev_join, s_side);
    } else {
        convert_half_kernel<<<(conv8 + T - 1) / T, T>>>(feat, xh, conv8);
        convert_weights_kernel<<<(18432 + T - 1) / T, T>>>(W0, W1, W2);
    }

    // ---- branch B (main stream): degrees + CSR build ------------------------
    zero_init_kernel<<<(NN + T - 1) / T, T>>>();
    degree_kernel<<<(nE + T - 1) / T, T>>>(src, dst, nE);
    scan1_kernel<<<NB, SCAN_BS>>>();
    scan2_kernel<<<1, 256>>>(NB);
    scan3_kernel<<<NB, SCAN_BS>>>(nE);
    fillcsr_kernel<<<(nE + T - 1) / T, T>>>(src, dst, nE);

    if (use_side) cudaStreamWaitEvent(0, ev_join, 0);

    // layer 0: aggh = A^T (xh * snorm); hh = relu((aggh * dnorm) @ W0)
    gather256h_kernel<<<gather_blocks, T>>>(xh, aggh);
    gemm_h_kernel<128, true><<<dim3(gemm_rows, 2), T>>>(aggh, w0h, dnorm, hh, NN, 256);

    // layer 1
    gather256h_kernel<<<gather_blocks, T>>>(hh, aggh);
    gemm_h_kernel<128, true><<<dim3(gemm_rows, 2), T>>>(aggh, w1h, dnorm, hh, NN, 256);

    // layer 2: xmh = (hh * snorm) @ W2; out = dnorm * (A^T xmh)
    gemm_h_kernel<64, false><<<dim3(gemm_rows, 1), T>>>(hh, w2h, snorm, xmh, NN, 64);
    gather64h_kernel<<<gather_blocks, T>>>(xmh, out);
}